// round 15
// baseline (speedup 1.0000x reference)
#include <cuda_runtime.h>
#include <cuda_bf16.h>
#include <cstdint>

// TemplateEncoder: out (B=2, N=1024, N=1024, 16) fp32 = 128 MiB.
//
// one_hot(bin,22) @ W + b -> LN -> ReLU depends only on bin: precompute a
// 22x16 table; out_row(b,i,j) = table[bin(i,j)] * min(conf_i, conf_j).
//
// Evidence across R3-R14: kernel is latency-bound (no pipe saturated;
// throughput tracks resident warps). Fix: grid = 1216 = 152 SMs x occ 8 ->
// exactly one FULL wave on GB300 (vs 1024 blocks = 71% occupancy before).
// The 2048 (batch,i) row-units are split into contiguous 1-2 row chunks;
// the batch boundary falls exactly at block 608, so every block stages one
// batch's j-data (16KB smem) and the 22x16 table once, then streams
// 16 coalesced float4-store tiles per row.

namespace {

constexpr int   TD    = 16;
constexpr float BIN_W = 40.0f / 21.0f;
constexpr float INV_W = 21.0f / 40.0f;
constexpr int   TBL_STRIDE = 20;   // floats; 80B rows, 16B aligned
constexpr int   GRID  = 1216;      // 152 SMs * 8 blocks
constexpr int   ROWS  = 2048;      // 2 batches * 1024 i-rows

__global__ __launch_bounds__(256, 8) void template_encoder_kernel(
    const float* __restrict__ coords,   // (B, N, 3)
    const float* __restrict__ conf,     // (B, N)
    const float* __restrict__ Wm,       // (22, 16)
    const float* __restrict__ bv,       // (16)
    const float* __restrict__ gam,      // (16)
    const float* __restrict__ bet,      // (16)
    float4* __restrict__ out)
{
    __shared__ float  table[22][TBL_STRIDE];
    __shared__ float4 s_j[1024];        // (x, y, z, conf) per j of this batch

    const int tid = threadIdx.x;
    const int g   = blockIdx.x;

    // contiguous row chunk; batch boundary (row 1024) is exact at g = 608
    const int start = (g * ROWS) / GRID;
    const int end   = ((g + 1) * ROWS) / GRID;   // start+1 or start+2
    const int batch = start >> 10;
    const int gb    = batch << 10;

    // ---- stage all 1024 j entries for this batch ----
    #pragma unroll
    for (int q = 0; q < 4; ++q) {
        const int j  = (q << 8) + tid;
        const int gj = gb + j;
        float4 v;
        v.x = coords[gj * 3 + 0];
        v.y = coords[gj * 3 + 1];
        v.z = coords[gj * 3 + 2];
        v.w = conf[gj];
        s_j[j] = v;
    }

    // ---- 22x16 bin table: relu(LN(W[k]+b)*gamma+beta) ----
    if (tid < 22) {
        float h[TD];
        float mu = 0.0f;
        #pragma unroll
        for (int d = 0; d < TD; ++d) { h[d] = Wm[tid * TD + d] + bv[d]; mu += h[d]; }
        mu *= (1.0f / TD);
        float var = 0.0f;
        #pragma unroll
        for (int d = 0; d < TD; ++d) { float t = h[d] - mu; var = fmaf(t, t, var); }
        var *= (1.0f / TD);
        const float inv = rsqrtf(var + 1e-5f);
        #pragma unroll
        for (int d = 0; d < TD; ++d)
            table[tid][d] = fmaxf((h[d] - mu) * inv * gam[d] + bet[d], 0.0f);
    }
    __syncthreads();

    const int jl   = tid >> 2;          // local j within a 64-row tile (4 thr/row)
    const int part = tid & 3;           // which float4 of the 16-float feature row

    for (int r = start; r < end; ++r) {
        const int   i   = r & 1023;
        const int   gi  = gb + i;
        const float cix = __ldg(coords + gi * 3 + 0);   // uniform across block
        const float ciy = __ldg(coords + gi * 3 + 1);
        const float ciz = __ldg(coords + gi * 3 + 2);
        const float cfi = __ldg(conf + gi);
        const bool  hi  = cfi > 0.0f;
        const int   base4 = gi << 12;                   // float4 index of row start

        #pragma unroll 2
        for (int k = 0; k < 16; ++k) {
            const float4 cj = s_j[(k << 6) + jl];       // broadcast LDS.128

            const float dx = cix - cj.x;
            const float dy = ciy - cj.y;
            const float dz = ciz - cj.z;
            const float dist =
                sqrtf(fmaf(dx, dx, fmaf(dy, dy, fmaf(dz, dz, 1e-8f))));

            // searchsorted(edges, dist, 'left'), clipped to [0,20]; exact vs
            // the same f32 edge values (m * BIN_W) the reference uses.
            int c = (int)(dist * INV_W);
            c = c > 21 ? 21 : c;
            const float fc = (float)c;
            int cnt = c;
            if (c     <= 20 &&  fc         * BIN_W < dist) ++cnt;
            if (c + 1 <= 20 && (fc + 1.0f) * BIN_W < dist) ++cnt;
            int bin = cnt > 20 ? 20 : cnt;
            if (!(hi && cj.w > 0.0f)) bin = 21;         // no_template_bin
            const float cp = fminf(cfi, cj.w);

            float4 v = *reinterpret_cast<const float4*>(&table[bin][part << 2]);
            v.x *= cp; v.y *= cp; v.z *= cp; v.w *= cp;

            out[base4 + (k << 8) + tid] = v;            // coalesced STG.128
        }
    }
}

} // namespace

extern "C" void kernel_launch(void* const* d_in, const int* in_sizes, int n_in,
                              void* d_out, int out_size) {
    const float* coords = (const float*)d_in[0];
    const float* conf   = (const float*)d_in[1];
    const float* Wm     = (const float*)d_in[2];
    const float* bv     = (const float*)d_in[3];
    const float* gam    = (const float*)d_in[4];
    const float* bet    = (const float*)d_in[5];
    template_encoder_kernel<<<GRID, 256>>>(coords, conf, Wm, bv, gam, bet,
                                           (float4*)d_out);
}